// round 1
// baseline (speedup 1.0000x reference)
#include <cuda_runtime.h>
#include <cuda_bf16.h>

// NeRF raw2outputs. One warp per ray; 192 samples = 6 chunks of 32.
// Exclusive cumprod of (1 - alpha + 1e-10) via warp product scan with a
// cross-chunk carry. All global accesses coalesced (float4 raw, float z).
//
// Output layout (tuple flattened in order), N = num rays:
//   [0 , 3N)        rgb_map   [N,3]
//   [3N, 4N)        disp_map  [N,1]
//   [4N, 5N)        acc_map   [N,1]
//   [5N, 197N)      weights   [N,192]
//   [197N, 198N)    depth_map [N,1]

#define FULL 0xffffffffu
#define NSAMP 192
#define NCHUNK 6
#define INF_DIST 1e10f

__global__ __launch_bounds__(256, 8)
void nerf_render_kernel(const float4* __restrict__ raw4,
                        const float*  __restrict__ z_vals,
                        const float*  __restrict__ rays_d,
                        float* __restrict__ out,
                        int N)
{
    const int warp_in_blk = threadIdx.x >> 5;
    const int lane        = threadIdx.x & 31;
    const int ray = blockIdx.x * (blockDim.x >> 5) + warp_in_blk;
    if (ray >= N) return;

    const long base = (long)ray * NSAMP;

    // ray direction norm (all lanes load same 3 addrs -> broadcast)
    const float dx = rays_d[3 * ray + 0];
    const float dy = rays_d[3 * ray + 1];
    const float dz = rays_d[3 * ray + 2];
    const float nrm = sqrtf(dx * dx + dy * dy + dz * dz);

    // preload all z values for this ray (coalesced, 6 regs)
    float zv[NCHUNK];
#pragma unroll
    for (int c = 0; c < NCHUNK; ++c)
        zv[c] = z_vals[base + c * 32 + lane];

    float* __restrict__ wout = out + (long)5 * N;

    float Tcarry = 1.0f;
    float r_sum = 0.f, g_sum = 0.f, b_sum = 0.f, d_sum = 0.f, a_sum = 0.f;

#pragma unroll
    for (int c = 0; c < NCHUNK; ++c) {
        const float4 rv = raw4[base + c * 32 + lane];
        const float z = zv[c];

        // dist to next sample; lane31 needs first z of next chunk; last sample = inf
        float zn = __shfl_down_sync(FULL, z, 1);
        float dist;
        if (c < NCHUNK - 1) {
            const float zfn = __shfl_sync(FULL, zv[c + 1], 0);
            dist = (lane == 31) ? (zfn - z) : (zn - z);
        } else {
            dist = (lane == 31) ? INF_DIST : (zn - z);
        }
        dist *= nrm;

        const float sigma = fmaxf(rv.w, 0.f);
        const float alpha = 1.f - __expf(-sigma * dist);
        const float t = 1.f - alpha + 1e-10f;

        // warp-inclusive product scan of t
        float p = t;
#pragma unroll
        for (int off = 1; off < 32; off <<= 1) {
            const float u = __shfl_up_sync(FULL, p, off);
            if (lane >= off) p *= u;
        }
        // exclusive prefix
        float exc = __shfl_up_sync(FULL, p, 1);
        if (lane == 0) exc = 1.f;

        const float Ti = Tcarry * exc;
        const float w  = alpha * Ti;
        Tcarry *= __shfl_sync(FULL, p, 31);   // carry total chunk product

        // sigmoid rgb
        const float sr = __fdividef(1.f, 1.f + __expf(-rv.x));
        const float sg = __fdividef(1.f, 1.f + __expf(-rv.y));
        const float sb = __fdividef(1.f, 1.f + __expf(-rv.z));

        r_sum += w * sr;
        g_sum += w * sg;
        b_sum += w * sb;
        d_sum += w * z;
        a_sum += w;

        wout[base + c * 32 + lane] = w;       // coalesced
    }

    // warp reductions
#pragma unroll
    for (int off = 16; off; off >>= 1) {
        r_sum += __shfl_down_sync(FULL, r_sum, off);
        g_sum += __shfl_down_sync(FULL, g_sum, off);
        b_sum += __shfl_down_sync(FULL, b_sum, off);
        d_sum += __shfl_down_sync(FULL, d_sum, off);
        a_sum += __shfl_down_sync(FULL, a_sum, off);
    }

    if (lane == 0) {
        out[3 * ray + 0] = r_sum;
        out[3 * ray + 1] = g_sum;
        out[3 * ray + 2] = b_sum;

        const float acc = a_sum;
        float depth = d_sum;
        if (acc <= 1e-10f) depth = INF_DIST;
        const float ratio = __fdividef(depth, acc);           // acc==0 -> inf
        const float disp  = __fdividef(1.f, fmaxf(1e-10f, ratio));

        out[(long)3 * N + ray] = disp;
        out[(long)4 * N + ray] = acc;
        out[(long)197 * N + ray] = depth;
    }
}

extern "C" void kernel_launch(void* const* d_in, const int* in_sizes, int n_in,
                              void* d_out, int out_size)
{
    const float4* raw4   = (const float4*)d_in[0];
    const float*  z_vals = (const float*)d_in[1];
    const float*  rays_d = (const float*)d_in[2];
    float* out = (float*)d_out;

    const int N = in_sizes[2] / 3;          // num rays from rays_d
    const int warps_per_blk = 8;            // 256 threads
    const int blocks = (N + warps_per_blk - 1) / warps_per_blk;
    nerf_render_kernel<<<blocks, warps_per_blk * 32>>>(raw4, z_vals, rays_d, out, N);
}

// round 2
// speedup vs baseline: 1.1046x; 1.1046x over previous
#include <cuda_runtime.h>
#include <cuda_bf16.h>

// NeRF raw2outputs. One warp per ray; 192 samples = 6 chunks of 32.
// R2: front-batched loads (MLP ~12 per warp) + ILP across the 6 independent
// warp product-scans; cross-chunk transmittance carry applied as a final
// prefix over chunk totals instead of a serial chain.
//
// Output layout (tuple flattened in order), N = num rays:
//   [0 , 3N)     rgb_map   [N,3]
//   [3N, 4N)     disp_map  [N,1]
//   [4N, 5N)     acc_map   [N,1]
//   [5N, 197N)   weights   [N,192]
//   [197N, 198N) depth_map [N,1]

#define FULL 0xffffffffu
#define NSAMP 192
#define NCHUNK 6
#define INF_DIST 1e10f

__global__ __launch_bounds__(256)
void nerf_render_kernel(const float4* __restrict__ raw4,
                        const float*  __restrict__ z_vals,
                        const float*  __restrict__ rays_d,
                        float* __restrict__ out,
                        int N)
{
    const int warp_in_blk = threadIdx.x >> 5;
    const int lane        = threadIdx.x & 31;
    const int ray = blockIdx.x * (blockDim.x >> 5) + warp_in_blk;
    if (ray >= N) return;

    const long base = (long)ray * NSAMP;

    // ---- front-batch ALL global loads (12 independent LDGs in flight) ----
    float4 rv[NCHUNK];
    float  zv[NCHUNK];
#pragma unroll
    for (int c = 0; c < NCHUNK; ++c)
        rv[c] = raw4[base + c * 32 + lane];
#pragma unroll
    for (int c = 0; c < NCHUNK; ++c)
        zv[c] = z_vals[base + c * 32 + lane];

    const float dx = rays_d[3 * ray + 0];
    const float dy = rays_d[3 * ray + 1];
    const float dz = rays_d[3 * ray + 2];
    const float nrm = sqrtf(dx * dx + dy * dy + dz * dz);

    // ---- per-sample alpha and t = 1-alpha+eps (independent across chunks) ----
    float alpha[NCHUNK], p[NCHUNK];
#pragma unroll
    for (int c = 0; c < NCHUNK; ++c) {
        const float z  = zv[c];
        const float zn = __shfl_down_sync(FULL, z, 1);
        float dist;
        if (c < NCHUNK - 1) {
            const float zfn = __shfl_sync(FULL, zv[c + 1], 0);
            dist = (lane == 31) ? (zfn - z) : (zn - z);
        } else {
            dist = (lane == 31) ? INF_DIST : (zn - z);
        }
        dist *= nrm;
        const float sigma = fmaxf(rv[c].w, 0.f);
        alpha[c] = 1.f - __expf(-sigma * dist);
        p[c] = 1.f - alpha[c] + 1e-10f;
    }

    // ---- 6 independent inclusive product scans, interleaved for ILP ----
#pragma unroll
    for (int off = 1; off < 32; off <<= 1) {
#pragma unroll
        for (int c = 0; c < NCHUNK; ++c) {
            const float u = __shfl_up_sync(FULL, p[c], off);
            if (lane >= off) p[c] *= u;
        }
    }

    // exclusive prefix within chunk + chunk totals (independent shuffles)
    float exc[NCHUNK], tot[NCHUNK];
#pragma unroll
    for (int c = 0; c < NCHUNK; ++c) {
        exc[c] = __shfl_up_sync(FULL, p[c], 1);
        if (lane == 0) exc[c] = 1.f;
        tot[c] = __shfl_sync(FULL, p[c], 31);
    }

    // cross-chunk carry prefix (6 scalar multiplies)
    float carry[NCHUNK];
    carry[0] = 1.f;
#pragma unroll
    for (int c = 1; c < NCHUNK; ++c)
        carry[c] = carry[c - 1] * tot[c - 1];

    // ---- weights, color/depth accumulation, stores ----
    float* __restrict__ wout = out + (long)5 * N;
    float r_sum = 0.f, g_sum = 0.f, b_sum = 0.f, d_sum = 0.f, a_sum = 0.f;

#pragma unroll
    for (int c = 0; c < NCHUNK; ++c) {
        const float w = alpha[c] * carry[c] * exc[c];

        const float sr = __fdividef(1.f, 1.f + __expf(-rv[c].x));
        const float sg = __fdividef(1.f, 1.f + __expf(-rv[c].y));
        const float sb = __fdividef(1.f, 1.f + __expf(-rv[c].z));

        r_sum += w * sr;
        g_sum += w * sg;
        b_sum += w * sb;
        d_sum += w * zv[c];
        a_sum += w;

        wout[base + c * 32 + lane] = w;   // coalesced
    }

    // ---- warp reductions ----
#pragma unroll
    for (int off = 16; off; off >>= 1) {
        r_sum += __shfl_down_sync(FULL, r_sum, off);
        g_sum += __shfl_down_sync(FULL, g_sum, off);
        b_sum += __shfl_down_sync(FULL, b_sum, off);
        d_sum += __shfl_down_sync(FULL, d_sum, off);
        a_sum += __shfl_down_sync(FULL, a_sum, off);
    }

    if (lane == 0) {
        out[3 * ray + 0] = r_sum;
        out[3 * ray + 1] = g_sum;
        out[3 * ray + 2] = b_sum;

        const float acc = a_sum;
        float depth = d_sum;
        if (acc <= 1e-10f) depth = INF_DIST;
        const float ratio = __fdividef(depth, acc);
        const float disp  = __fdividef(1.f, fmaxf(1e-10f, ratio));

        out[(long)3 * N + ray]   = disp;
        out[(long)4 * N + ray]   = acc;
        out[(long)197 * N + ray] = depth;
    }
}

extern "C" void kernel_launch(void* const* d_in, const int* in_sizes, int n_in,
                              void* d_out, int out_size)
{
    const float4* raw4   = (const float4*)d_in[0];
    const float*  z_vals = (const float*)d_in[1];
    const float*  rays_d = (const float*)d_in[2];
    float* out = (float*)d_out;

    const int N = in_sizes[2] / 3;          // num rays from rays_d
    const int warps_per_blk = 8;            // 256 threads
    const int blocks = (N + warps_per_blk - 1) / warps_per_blk;
    nerf_render_kernel<<<blocks, warps_per_blk * 32>>>(raw4, z_vals, rays_d, out, N);
}